// round 2
// baseline (speedup 1.0000x reference)
#include <cuda_runtime.h>

// Problem constants (match reference: N=50000, M=8192, C=768, NUM_BATCH=4, GRID=128)
#define NPTS_MAX 50000
#define MTGT_MAX 8192
#define CCH      768
#define NB       4

#define TPB   256     // search threads per block (1 target per thread)
#define TILE  1024    // shared-memory coord tile (int4 = 16KB)
#define SEGS  16      // N-dimension segments per batch

// ------- device scratch (static; no allocation anywhere) -------
__device__ int4     g_cbucket[NPTS_MAX];   // coords bucketed by batch: (x,y,z,orig_idx)
__device__ int4     g_tbucket[MTGT_MAX];   // targets bucketed by batch: (x,y,z,orig_idx)
__device__ unsigned g_best[MTGT_MAX];      // packed (d2<<16)|src_idx, 0xFFFFFFFF = none
__device__ int      g_ccount[NB], g_tcount[NB];
__device__ int      g_ccur[NB],   g_tcur[NB];
__device__ int      g_cbase[NB + 1], g_tbase[NB + 1];

// ------- kernel 0: reset per-replay state -------
__global__ void k_init(int m) {
    int i = blockIdx.x * blockDim.x + threadIdx.x;
    if (i < m) g_best[i] = 0xFFFFFFFFu;
    if (i < NB) { g_ccount[i] = 0; g_tcount[i] = 0; }
}

// ------- kernel 1/2: count per-batch sizes (block-aggregated) -------
__global__ void k_count(const int4* __restrict__ coords, int n, int is_target) {
    __shared__ int s[NB];
    if (threadIdx.x < NB) s[threadIdx.x] = 0;
    __syncthreads();
    int i = blockIdx.x * blockDim.x + threadIdx.x;
    if (i < n) atomicAdd(&s[coords[i].x & (NB - 1)], 1);
    __syncthreads();
    if (threadIdx.x < NB && s[threadIdx.x]) {
        int* cnt = is_target ? g_tcount : g_ccount;
        atomicAdd(&cnt[threadIdx.x], s[threadIdx.x]);
    }
}

// ------- kernel 3: exclusive prefix (tiny, 1 thread) -------
__global__ void k_prefix() {
    int c = 0, t = 0;
    for (int b = 0; b < NB; b++) {
        g_cbase[b] = c; g_ccur[b] = c; c += g_ccount[b];
        g_tbase[b] = t; g_tcur[b] = t; t += g_tcount[b];
    }
    g_cbase[NB] = c;
    g_tbase[NB] = t;
}

// ------- kernel 4/5: warp-aggregated scatter into batch buckets -------
__global__ void k_scatter(const int4* __restrict__ coords, int n, int is_target) {
    int i = blockIdx.x * blockDim.x + threadIdx.x;
    if (i >= n) return;
    int4 r = coords[i];                       // (batch, x, y, z) in one LDG.128
    int b = r.x & (NB - 1);
    int* cur = is_target ? g_tcur : g_ccur;
    int4* bucket = is_target ? g_tbucket : g_cbucket;

    unsigned mask = __match_any_sync(__activemask(), b);
    int lane   = threadIdx.x & 31;
    int leader = __ffs(mask) - 1;
    int pos = 0;
    if (lane == leader) pos = atomicAdd(&cur[b], __popc(mask));
    pos = __shfl_sync(mask, pos, leader);
    pos += __popc(mask & ((1u << lane) - 1u));
    bucket[pos] = make_int4(r.y, r.z, r.w, i);
}

// ------- kernel 6: brute-force NN search within batch, packed-key min -------
// grid: (target_tiles, SEGS, NB). Blocks out of range exit immediately.
__global__ void __launch_bounds__(TPB) k_search() {
    int b = blockIdx.z;
    int tlo = g_tbase[b], thi = g_tbase[b + 1];
    int tstart = tlo + blockIdx.x * TPB;
    if (tstart >= thi) return;
    int clo = g_cbase[b], chi = g_cbase[b + 1];
    int ccount = chi - clo;
    if (ccount <= 0) return;
    int seg = (ccount + SEGS - 1) / SEGS;
    int cs = clo + blockIdx.y * seg;
    int ce = min(cs + seg, chi);
    if (cs >= ce) return;

    __shared__ int4 sh[TILE];

    int ti = tstart + threadIdx.x;
    bool active = ti < thi;
    int4 t = active ? g_tbucket[ti] : make_int4(0, 0, 0, 0);
    unsigned bestk = 0xFFFFFFFFu;

    for (int c = cs; c < ce; c += TILE) {
        int n = min(TILE, ce - c);
        for (int j = threadIdx.x; j < n; j += TPB) sh[j] = g_cbucket[c + j];
        __syncthreads();
        #pragma unroll 8
        for (int j = 0; j < n; j++) {
            int4 p = sh[j];                       // LDS.128 broadcast (conflict-free)
            int dx = t.x - p.x;
            int dy = t.y - p.y;
            int dz = t.z - p.z;
            int d2 = dx * dx + dy * dy + dz * dz; // <= 3*127^2 < 2^16
            unsigned key = ((unsigned)d2 << 16) | (unsigned)p.w; // idx < 2^16
            bestk = min(bestk, key);
        }
        __syncthreads();
    }
    if (active) atomicMin(&g_best[t.w], bestk);
}

// ------- kernel 7: gather feature rows (or zeros if batch empty) -------
__global__ void k_gather(const float* __restrict__ feat, float* __restrict__ out) {
    int m = blockIdx.x;
    unsigned k = g_best[m];
    float4* o = (float4*)(out + (size_t)m * CCH);
    int j = threadIdx.x;                      // blockDim = CCH/4 = 192
    if (k == 0xFFFFFFFFu) {
        o[j] = make_float4(0.f, 0.f, 0.f, 0.f);
    } else {
        const float4* f = (const float4*)(feat + (size_t)(k & 0xFFFFu) * CCH);
        o[j] = f[j];
    }
}

extern "C" void kernel_launch(void* const* d_in, const int* in_sizes, int n_in,
                              void* d_out, int out_size) {
    const float* feat    = (const float*)d_in[0];
    const int4*  coords  = (const int4*)d_in[1];
    const int4*  tcoords = (const int4*)d_in[2];
    float*       out     = (float*)d_out;

    int n = in_sizes[1] / 4;   // 50000
    int m = in_sizes[2] / 4;   // 8192

    int init_blocks = ((m > NB ? m : NB) + 255) / 256;
    k_init<<<init_blocks, 256>>>(m);

    k_count<<<(n + 255) / 256, 256>>>(coords, n, 0);
    k_count<<<(m + 255) / 256, 256>>>(tcoords, m, 1);
    k_prefix<<<1, 1>>>();
    k_scatter<<<(n + 255) / 256, 256>>>(coords, n, 0);
    k_scatter<<<(m + 255) / 256, 256>>>(tcoords, m, 1);

    int tiles = (m + TPB - 1) / TPB;           // worst case: all targets in one batch
    dim3 sgrid(tiles, SEGS, NB);
    k_search<<<sgrid, TPB>>>();

    k_gather<<<m, CCH / 4>>>(feat, out);
}

// round 3
// speedup vs baseline: 1.8566x; 1.8566x over previous
#include <cuda_runtime.h>

// Problem constants (reference: N=50000, M=8192, C=768, NUM_BATCH=4, GRID=128)
#define NPTS_MAX 50000
#define MTGT_MAX 8192
#define CCH      768
#define NB       4

#define TPB   256     // search threads per block (1 target per thread)
#define TILE  2048    // shared-memory candidate tile (int2 = 16KB)
#define SEGS  16      // candidate-dimension segments per batch

// ------- device scratch (static; no allocation anywhere) -------
// Fixed-capacity per-batch regions: batch b owns [b*CAP, b*CAP + count_b)
__device__ int2     g_cbucket[NB * NPTS_MAX];  // (packed_xyz, orig_idx)
__device__ int2     g_tbucket[NB * MTGT_MAX];  // (packed_xyz, orig_idx)
__device__ unsigned g_best[MTGT_MAX];          // (d2<<16)|src_idx, 0xFFFFFFFF = none
__device__ int      g_ccur[NB], g_tcur[NB];    // alloc cursors == final counts

// ------- kernel 0: reset per-replay state -------
__global__ void k_init(int m) {
    int i = blockIdx.x * blockDim.x + threadIdx.x;
    if (i < m) g_best[i] = 0xFFFFFFFFu;
    if (i < NB) { g_ccur[i] = 0; g_tcur[i] = 0; }
}

// ------- kernel 1: fused warp-aggregated scatter (coords + targets) -------
__global__ void k_scatter_all(const int4* __restrict__ coords, int n,
                              const int4* __restrict__ tcoords, int m) {
    int i = blockIdx.x * blockDim.x + threadIdx.x;
    if (i < n) {
        int4 r = coords[i];                       // (batch,x,y,z) one LDG.128
        int b = r.x & (NB - 1);
        unsigned mask = __match_any_sync(__activemask(), b);
        int lane = threadIdx.x & 31;
        int leader = __ffs(mask) - 1;
        int pos = 0;
        if (lane == leader) pos = atomicAdd(&g_ccur[b], __popc(mask));
        pos = __shfl_sync(mask, pos, leader);
        pos += __popc(mask & ((1u << lane) - 1u));
        int packed = r.y | (r.z << 8) | (r.w << 16);   // bytes: x,y,z,0
        g_cbucket[b * NPTS_MAX + pos] = make_int2(packed, i);
    } else if (i < n + m) {
        int j = i - n;
        int4 r = tcoords[j];
        int b = r.x & (NB - 1);
        unsigned mask = __match_any_sync(__activemask(), b);
        int lane = threadIdx.x & 31;
        int leader = __ffs(mask) - 1;
        int pos = 0;
        if (lane == leader) pos = atomicAdd(&g_tcur[b], __popc(mask));
        pos = __shfl_sync(mask, pos, leader);
        pos += __popc(mask & ((1u << lane) - 1u));
        int packed = r.y | (r.z << 8) | (r.w << 16);
        g_tbucket[b * MTGT_MAX + pos] = make_int2(packed, j);
    }
}

// ------- kernel 2: brute-force NN search, SIMD byte distance, packed-key min --
// grid: (target_tiles, SEGS, NB); out-of-range blocks exit immediately.
__global__ void __launch_bounds__(TPB) k_search() {
    int b = blockIdx.z;
    int tcount = g_tcur[b];
    int tstart = blockIdx.x * TPB;
    if (tstart >= tcount) return;
    int ccount = g_ccur[b];
    if (ccount <= 0) return;                     // empty batch -> best stays 0xFFFFFFFF
    int seg = (ccount + SEGS - 1) / SEGS;
    int cs = blockIdx.y * seg;
    int ce = min(cs + seg, ccount);
    if (cs >= ce) return;

    const int2* cb = g_cbucket + b * NPTS_MAX;
    __shared__ int2 sh[TILE];

    int ti = tstart + threadIdx.x;
    bool active = ti < tcount;
    int2 t = active ? g_tbucket[b * MTGT_MAX + ti] : make_int2(0, 0);
    unsigned tp = (unsigned)t.x;
    unsigned bestk = 0xFFFFFFFFu;

    for (int c = cs; c < ce; c += TILE) {
        int nn = min(TILE, ce - c);
        for (int j = threadIdx.x; j < nn; j += TPB) sh[j] = cb[c + j];
        __syncthreads();
        #pragma unroll 8
        for (int j = 0; j < nn; j++) {
            int2 p = sh[j];                                  // LDS.64 broadcast
            unsigned ad = __vabsdiffu4(tp, (unsigned)p.x);   // per-byte |dx|,|dy|,|dz|,0
            unsigned d2 = __dp4a(ad, ad, 0u);                // dx^2+dy^2+dz^2 (<2^16)
            unsigned key = d2 * 65536u + (unsigned)p.y;      // one IMAD; idx<2^16
            bestk = min(bestk, key);
        }
        __syncthreads();
    }
    if (active) atomicMin(&g_best[t.y], bestk);
}

// ------- kernel 3: gather feature rows (zeros if batch empty) -------
__global__ void k_gather(const float* __restrict__ feat, float* __restrict__ out) {
    int m = blockIdx.x;
    unsigned k = g_best[m];
    float4* o = (float4*)(out + (size_t)m * CCH);
    int j = threadIdx.x;                      // blockDim = CCH/4 = 192
    if (k == 0xFFFFFFFFu) {
        o[j] = make_float4(0.f, 0.f, 0.f, 0.f);
    } else {
        const float4* f = (const float4*)(feat + (size_t)(k & 0xFFFFu) * CCH);
        o[j] = f[j];
    }
}

extern "C" void kernel_launch(void* const* d_in, const int* in_sizes, int n_in,
                              void* d_out, int out_size) {
    const float* feat    = (const float*)d_in[0];
    const int4*  coords  = (const int4*)d_in[1];
    const int4*  tcoords = (const int4*)d_in[2];
    float*       out     = (float*)d_out;

    int n = in_sizes[1] / 4;   // 50000
    int m = in_sizes[2] / 4;   // 8192

    int init_blocks = ((m > NB ? m : NB) + 255) / 256;
    k_init<<<init_blocks, 256>>>(m);

    k_scatter_all<<<(n + m + 255) / 256, 256>>>(coords, n, tcoords, m);

    int tiles = (m + TPB - 1) / TPB;           // worst case: all targets in one batch
    dim3 sgrid(tiles, SEGS, NB);
    k_search<<<sgrid, TPB>>>();

    k_gather<<<m, CCH / 4>>>(feat, out);
}